// round 16
// baseline (speedup 1.0000x reference)
#include <cuda_runtime.h>
#include <cuda_bf16.h>
#include <cuda_fp16.h>
#include <math.h>
#include <stdint.h>

// Problem constants: N=200000, K_IN=8, K_OUT=4, E=800000, D=64, H=128, O=1
#define D_DIM 64
#define K_IN 8
#define K_OUT 4
#define H_DIM 128
#define TILE_M 64
#define N_TILES 12500       // 800000 rows / 64 rows per tile
#define GRID_CTAS 296       // 2 persistent CTAs per SM

// ---------------------------------------------------------------------------
// helpers
// ---------------------------------------------------------------------------
__device__ __forceinline__ uint32_t smem_u32(const void* p) {
    uint32_t a;
    asm("{ .reg .u64 t; cvta.to.shared.u64 t, %1; cvt.u32.u64 %0, t; }"
        : "=r"(a) : "l"(p));
    return a;
}

// pack two floats to f16x2: lo -> bits[15:0], hi -> bits[31:16]
__device__ __forceinline__ uint32_t f16x2_rn(float lo, float hi) {
    uint32_t r;
    asm("cvt.rn.f16x2.f32 %0, %1, %2;" : "=r"(r) : "f"(hi), "f"(lo));
    return r;
}

// convert 8 fp32 to single fp16 16B chunk
__device__ __forceinline__ uint4 cvt8h(const float* f) {
    uint4 v;
    v.x = f16x2_rn(f[0], f[1]); v.y = f16x2_rn(f[2], f[3]);
    v.z = f16x2_rn(f[4], f[5]); v.w = f16x2_rn(f[6], f[7]);
    return v;
}

#define LDMX4(r0, r1, r2, r3, addr) \
    asm volatile("ldmatrix.sync.aligned.m8n8.x4.shared.b16 {%0,%1,%2,%3}, [%4];" \
        : "=r"(r0), "=r"(r1), "=r"(r2), "=r"(r3) : "r"(addr))

#define MMAF16(c, a, b) \
    asm volatile("mma.sync.aligned.m16n8k16.row.col.f32.f16.f16.f32 " \
        "{%0,%1,%2,%3}, {%4,%5,%6,%7}, {%8,%9}, {%0,%1,%2,%3};" \
        : "+f"((c)[0]), "+f"((c)[1]), "+f"((c)[2]), "+f"((c)[3]) \
        : "r"((a)[0]), "r"((a)[1]), "r"((a)[2]), "r"((a)[3]), \
          "r"((b)[0]), "r"((b)[1]))

// ---------------------------------------------------------------------------
// SMEM layout (bytes), TWO CTAs per SM:
//   XB  @ 0      [64 m][128 k] fp16 X    (16 KB)  256B rows, XOR-16B swizzle
//   HB  @ 16384  [64 m][128 h] fp16 H    (16 KB)
//   W0  @ 32768  [128 h][128 k] fp16     (32 KB)
//   W1  @ 65536  (32 KB)
//   STG @ 98304  4 x 64 fp32 partials (1 KB)
// Total 99328 bytes per CTA -> 2 CTAs/SM.
// ---------------------------------------------------------------------------
#define XB_B    0u
#define HB_B    16384u
#define W0_B    32768u
#define W1_B    65536u
#define STG_B   98304u
#define SMEM_TOTAL 99328

__device__ __forceinline__ uint32_t swz(int row, int chunk) {
    return (uint32_t)row * 256u + (uint32_t)((chunk ^ (row & 7)) << 4);
}

// 1-pass GEMM over k=128 (A single fp16), warp tile 64m x 32n: acc += A * W
// A: full 64 rows (4 x 16m blocks, +4096B apart). B: 32 n rows at bOff0/bOff1.
__device__ __forceinline__ void gemm_64x32(
    uint32_t AB, uint32_t WB,
    uint32_t aBase, uint32_t aKey, uint32_t cbA,
    uint32_t bOff0, uint32_t bOff1, uint32_t bKey, uint32_t cbB,
    float acc[4][4][4])
{
#pragma unroll
    for (int kc = 0; kc < 8; ++kc) {
        uint32_t ca = (uint32_t)((((uint32_t)(2 * kc) + cbA) ^ aKey) << 4);
        uint32_t cb = (uint32_t)((((uint32_t)(2 * kc) + cbB) ^ bKey) << 4);
        uint32_t a[4][4], bq0[4], bq1[4];
#pragma unroll
        for (int i = 0; i < 4; ++i)
            LDMX4(a[i][0], a[i][1], a[i][2], a[i][3],
                  AB + aBase + (uint32_t)(i * 4096) + ca);
        LDMX4(bq0[0], bq0[1], bq0[2], bq0[3], WB + bOff0 + cb);
        LDMX4(bq1[0], bq1[1], bq1[2], bq1[3], WB + bOff1 + cb);
#pragma unroll
        for (int i = 0; i < 4; ++i) {
            MMAF16(acc[i][0], a[i], bq0 + 0);
            MMAF16(acc[i][1], a[i], bq0 + 2);
            MMAF16(acc[i][2], a[i], bq1 + 0);
            MMAF16(acc[i][3], a[i], bq1 + 2);
        }
    }
}

// ---------------------------------------------------------------------------
// Register-only attention for one node (see R12 notes). Pooled written
// directly into X pooled-half (single fp16) rows 4*nlocal..+3, cols 64..127.
// ---------------------------------------------------------------------------
__device__ __forceinline__ void attn_node(
    const float2* r, int m_l, int ln, char* smem, int nlocal)
{
    const unsigned FULL = 0xffffffffu;
    const int sel1 = (ln >> 4) & 1;
    const int sel2 = (ln >> 3) & 1;
    const int sel3 = (ln >> 2) & 1;
    const int sel4 = (ln >> 1) & 1;
    const int sel5 = ln & 1;

    float h1[32];
#pragma unroll
    for (int i = 0; i < 32; ++i) {
        const int qa = i >> 3, ka = i & 7;
        float da = r[qa].x * r[ka].x + r[qa].y * r[ka].y;
        float db = r[qa + 4].x * r[ka].x + r[qa + 4].y * r[ka].y;
        float mine  = sel1 ? db : da;
        float their = sel1 ? da : db;
        h1[i] = mine + __shfl_xor_sync(FULL, their, 16);
    }
    float h2[16];
#pragma unroll
    for (int i = 0; i < 16; ++i) {
        float mine  = sel2 ? h1[i + 16] : h1[i];
        float their = sel2 ? h1[i] : h1[i + 16];
        h2[i] = mine + __shfl_xor_sync(FULL, their, 8);
    }
    float h3[8];
#pragma unroll
    for (int i = 0; i < 8; ++i) {
        float mine  = sel3 ? h2[i + 8] : h2[i];
        float their = sel3 ? h2[i] : h2[i + 8];
        h3[i] = mine + __shfl_xor_sync(FULL, their, 4);
    }
    float h4[4];
#pragma unroll
    for (int i = 0; i < 4; ++i) {
        float mine  = sel4 ? h3[i + 4] : h3[i];
        float their = sel4 ? h3[i] : h3[i + 4];
        h4[i] = mine + __shfl_xor_sync(FULL, their, 2);
    }
    float s0, s1;
    {
        float mine0  = sel5 ? h4[2] : h4[0];
        float their0 = sel5 ? h4[0] : h4[2];
        float mine1  = sel5 ? h4[3] : h4[1];
        float their1 = sel5 ? h4[1] : h4[3];
        s0 = (mine0 + __shfl_xor_sync(FULL, their0, 1)) * 0.125f;
        s1 = (mine1 + __shfl_xor_sync(FULL, their1, 1)) * 0.125f;
    }

    const int k0 = 2 * (ln & 3);
    int mk0 = __shfl_sync(FULL, m_l, k0);
    int mk1 = __shfl_sync(FULL, m_l, k0 + 1);
    if (!mk0) s0 = -1e9f;
    if (!mk1) s1 = -1e9f;

    float mx = fmaxf(s0, s1);
    mx = fmaxf(mx, __shfl_xor_sync(FULL, mx, 1));
    mx = fmaxf(mx, __shfl_xor_sync(FULL, mx, 2));
    float e0 = __expf(s0 - mx), e1 = __expf(s1 - mx);
    float z = e0 + e1;
    z += __shfl_xor_sync(FULL, z, 1);
    z += __shfl_xor_sync(FULL, z, 2);
    float a0 = e0 / z, a1 = e1 / z;

    int mq = __shfl_sync(FULL, m_l, ln >> 2);
    float v0 = mq ? a0 : 0.f, v1 = mq ? a1 : 0.f;
#pragma unroll
    for (int o = 4; o < 32; o <<= 1) {
        v0 += __shfl_xor_sync(FULL, v0, o);
        v1 += __shfl_xor_sync(FULL, v1, o);
    }
    int cnt = __popc(__ballot_sync(FULL, m_l != 0));
    float inv_denom = 1.f / fmaxf((float)cnt, 1.f);

    float px = 0.f, py = 0.f;
#pragma unroll
    for (int k = 0; k < 8; ++k) {
        float wk = (k & 1) ? __shfl_sync(FULL, v1, k >> 1)
                           : __shfl_sync(FULL, v0, k >> 1);
        px += wk * r[k].x;
        py += wk * r[k].y;
    }
    px *= inv_denom;
    py *= inv_denom;

    uint32_t hw = f16x2_rn(px, py);
    const int chunk = 8 + (ln >> 2);
    const uint32_t cof = (uint32_t)((ln & 3) * 4);
#pragma unroll
    for (int rr = 0; rr < 4; ++rr) {
        int row = nlocal * 4 + rr;
        uint32_t off = (uint32_t)row * 256u
                     + (uint32_t)((chunk ^ (row & 7)) << 4) + cof;
        *(uint32_t*)(smem + XB_B + off) = hw;
    }
}

// ---------------------------------------------------------------------------
// attention (4 nodes/warp, processed in prefetched pairs) + edge-half X fill.
// ---------------------------------------------------------------------------
__device__ __forceinline__ void attn_and_fill(
    const float* __restrict__ edges, char* smem,
    const int* idx, const int* msk, int eidx,
    int lane, int w, int xrow, int xhalf)
{
    const unsigned FULL = 0xffffffffu;

    // ---- edge-half X fill first (issue GMEM loads early) ----
    {
        const float4* s4 = (const float4*)(edges + (size_t)eidx * D_DIM
                                           + xhalf * 32);
#pragma unroll
        for (int c = 0; c < 4; ++c) {
            float4 f0 = s4[2 * c], f1 = s4[2 * c + 1];
            float f[8] = {f0.x, f0.y, f0.z, f0.w, f1.x, f1.y, f1.z, f1.w};
            *(uint4*)(smem + XB_B + swz(xrow, xhalf * 4 + c)) = cvt8h(f);
        }
    }

    // ---- 4 nodes in 2 prefetched pairs ----
#pragma unroll
    for (int p = 0; p < 2; ++p) {
        float2 rA[K_IN], rB[K_IN];
#pragma unroll
        for (int k = 0; k < K_IN; ++k) {
            int ek = __shfl_sync(FULL, idx[2 * p], k);
            rA[k] = *(const float2*)(edges + (size_t)ek * D_DIM + lane * 2);
        }
#pragma unroll
        for (int k = 0; k < K_IN; ++k) {
            int ek = __shfl_sync(FULL, idx[2 * p + 1], k);
            rB[k] = *(const float2*)(edges + (size_t)ek * D_DIM + lane * 2);
        }
        attn_node(rA, msk[2 * p],     lane, smem, w * 4 + 2 * p);
        attn_node(rB, msk[2 * p + 1], lane, smem, w * 4 + 2 * p + 1);
    }
}

// ---------------------------------------------------------------------------
// Persistent fused kernel, software-pipelined, 128 threads (4 warps),
// warp tile 64m x 32n, 2 CTAs/SM.
//   loop: prefetch idx(next); GEMM1; epi1; B; attn+fill(next); GEMM2; epi2;
//         stage; C; out
// ---------------------------------------------------------------------------
__global__ void __launch_bounds__(128, 2) fused_kernel(
    const float* __restrict__ edges,
    const int* __restrict__ in_idx,
    const int* __restrict__ in_mask,
    const int* __restrict__ out_idx,
    const int* __restrict__ out_mask,
    const float* __restrict__ W0,
    const float* __restrict__ b0,
    const float* __restrict__ W1,
    const float* __restrict__ b1,
    const float* __restrict__ Wout,
    const float* __restrict__ bout,
    float* __restrict__ out)
{
    extern __shared__ char smem[];
    const uint32_t sb = smem_u32(smem);
    const unsigned FULL = 0xffffffffu;

    const int t    = threadIdx.x;
    const int lane = t & 31;
    const int w    = t >> 5;        // 0..3

    // ---- load W0/W1 -> single fp16 smem, ONCE (1 thread per row) ----
    {
        const int h = t;            // 0..127
        const int key = h & 7;
        const float4* s0 = (const float4*)(W0 + (size_t)h * H_DIM);
        const float4* s1 = (const float4*)(W1 + (size_t)h * H_DIM);
#pragma unroll
        for (int c = 0; c < 16; ++c) {
            uint32_t off = (uint32_t)h * 256u + (uint32_t)((c ^ key) << 4);
            {
                float4 f0 = s0[2 * c], f1 = s0[2 * c + 1];
                float f[8] = {f0.x, f0.y, f0.z, f0.w, f1.x, f1.y, f1.z, f1.w};
                *(uint4*)(smem + W0_B + off) = cvt8h(f);
            }
            {
                float4 f0 = s1[2 * c], f1 = s1[2 * c + 1];
                float f[8] = {f0.x, f0.y, f0.z, f0.w, f1.x, f1.y, f1.z, f1.w};
                *(uint4*)(smem + W1_B + off) = cvt8h(f);
            }
        }
    }

    // ---- per-lane GEMM geometry (warp tile 64m x 32n, n0 = w*32) ----
    const int n0  = w * 32;
    const int gid = lane >> 2;      // 0..7
    const int tig = lane & 3;       // 0..3
    const int sub = lane >> 3;      // 0..3
    const int r8  = lane & 7;
    const uint32_t aBase = (uint32_t)((sub & 1) * 8 + r8) * 256u;
    const uint32_t aKey  = (uint32_t)r8;
    const uint32_t cbA   = (uint32_t)(sub >> 1);
    const int bRow = n0 + (sub >> 1) * 8 + r8;
    const uint32_t bOff0 = (uint32_t)bRow * 256u;
    const uint32_t bOff1 = (uint32_t)(bRow + 16) * 256u;
    const uint32_t bKey  = (uint32_t)r8;
    const uint32_t cbB   = (uint32_t)(sub & 1);

    float* stage = (float*)(smem + STG_B);

    // X-fill roles: 2 threads per row, 4 chunks (32 k) each
    const int xrow  = t & 63;
    const int xhalf = t >> 6;       // 0..1

    // ---- prologue: first tile's attention + X fill ----
    int tile = blockIdx.x;
    {
        const int nodeA = tile * 16 + w * 4;
        int idx[4] = {0, 0, 0, 0}, msk[4] = {0, 0, 0, 0};
        if (lane < K_IN) {
#pragma unroll
            for (int p = 0; p < 4; ++p) {
                idx[p] = in_idx[(size_t)(nodeA + p) * K_IN + lane];
                msk[p] = in_mask[(size_t)(nodeA + p) * K_IN + lane];
            }
        }
        int eidx = out_idx[(size_t)tile * TILE_M + xrow];
        attn_and_fill(edges, smem, idx, msk, eidx, lane, w, xrow, xhalf);
    }
    __syncthreads();   // X + W ready

    for (; tile < N_TILES; tile += gridDim.x) {
        const long base = (long)tile * TILE_M;
        const int next = tile + (int)gridDim.x;
        const bool hasNext = (next < N_TILES);

        // ---- prefetch next-tile indices (latency hides under GEMM1) ----
        int nIdx[4] = {0, 0, 0, 0}, nMsk[4] = {0, 0, 0, 0}, nEidx = 0;
        if (hasNext) {
            const int nodeA = next * 16 + w * 4;
            if (lane < K_IN) {
#pragma unroll
                for (int p = 0; p < 4; ++p) {
                    nIdx[p] = in_idx[(size_t)(nodeA + p) * K_IN + lane];
                    nMsk[p] = in_mask[(size_t)(nodeA + p) * K_IN + lane];
                }
            }
            nEidx = out_idx[(size_t)next * TILE_M + xrow];
        }

        // ============ GEMM layer 1 (A = XB) ============
        float acc[4][4][4];
#pragma unroll
        for (int i = 0; i < 4; ++i)
#pragma unroll
            for (int j = 0; j < 4; ++j)
#pragma unroll
                for (int p = 0; p < 4; ++p) acc[i][j][p] = 0.f;

        gemm_64x32(sb + XB_B, sb + W0_B,
                   aBase, aKey, cbA, bOff0, bOff1, bKey, cbB, acc);

        // ---- epilogue 1: H = relu(acc + b0) -> HB ----
#pragma unroll
        for (int j = 0; j < 4; ++j) {
            int h0 = n0 + 8 * j + 2 * tig;
            float2 bb = *(const float2*)(b0 + h0);
            int chunk = (n0 + 8 * j) >> 3;
            uint32_t cof = (uint32_t)(tig * 4);
#pragma unroll
            for (int i = 0; i < 4; ++i) {
#pragma unroll
                for (int rs = 0; rs < 2; ++rs) {
                    int row = 16 * i + 8 * rs + gid;
                    float v0 = fmaxf(acc[i][j][2 * rs]     + bb.x, 0.f);
                    float v1 = fmaxf(acc[i][j][2 * rs + 1] + bb.y, 0.f);
                    uint32_t hw = f16x2_rn(v0, v1);
                    uint32_t off = (uint32_t)row * 256u
                                 + (uint32_t)((chunk ^ (row & 7)) << 4) + cof;
                    *(uint32_t*)(smem + HB_B + off) = hw;
                }
            }
        }
        __syncthreads();   // barrier B: HB ready; XB reads complete (XB dead)

        // ---- next tile's attention + X fill into (dead) XB ----
        if (hasNext) {
            attn_and_fill(edges, smem, nIdx, nMsk, nEidx,
                          lane, w, xrow, xhalf);
        }

        // ============ GEMM layer 2 (A = HB) ============
#pragma unroll
        for (int i = 0; i < 4; ++i)
#pragma unroll
            for (int j = 0; j < 4; ++j)
#pragma unroll
                for (int p = 0; p < 4; ++p) acc[i][j][p] = 0.f;

        gemm_64x32(sb + HB_B, sb + W1_B,
                   aBase, aKey, cbA, bOff0, bOff1, bKey, cbB, acc);

        // ---- final epilogue: relu(+b1), dot Wout, reduce ----
        float y[4][2];
#pragma unroll
        for (int i = 0; i < 4; ++i) { y[i][0] = 0.f; y[i][1] = 0.f; }
#pragma unroll
        for (int j = 0; j < 4; ++j) {
            int h0 = n0 + 8 * j + 2 * tig;
            float2 bb = *(const float2*)(b1 + h0);
            float2 ww = *(const float2*)(Wout + h0);
#pragma unroll
            for (int i = 0; i < 4; ++i) {
#pragma unroll
                for (int rs = 0; rs < 2; ++rs) {
                    float v0 = fmaxf(acc[i][j][2 * rs]     + bb.x, 0.f);
                    float v1 = fmaxf(acc[i][j][2 * rs + 1] + bb.y, 0.f);
                    y[i][rs] += ww.x * v0 + ww.y * v1;
                }
            }
        }
#pragma unroll
        for (int i = 0; i < 4; ++i)
#pragma unroll
            for (int rs = 0; rs < 2; ++rs) {
                y[i][rs] += __shfl_xor_sync(FULL, y[i][rs], 1);
                y[i][rs] += __shfl_xor_sync(FULL, y[i][rs], 2);
            }

        if (tig == 0) {
#pragma unroll
            for (int i = 0; i < 4; ++i)
#pragma unroll
                for (int rs = 0; rs < 2; ++rs) {
                    int row = 16 * i + 8 * rs + gid;
                    stage[w * TILE_M + row] = y[i][rs];
                }
        }
        __syncthreads();   // barrier C: stage ready; XB writes complete

        if (t < TILE_M) {
            long row = base + t;
            float s = stage[t] + stage[64 + t] + stage[128 + t]
                    + stage[192 + t] + bout[0];
            out[row] = s * (float)out_mask[row];
        }
        // no barrier D (hazards covered by B'/C; see R15 analysis)
    }
}

// ---------------------------------------------------------------------------
extern "C" void kernel_launch(void* const* d_in, const int* in_sizes, int n_in,
                              void* d_out, int out_size) {
    const float* edges   = (const float*)d_in[0];
    const int*   in_idx  = (const int*)d_in[1];
    const int*   in_mask = (const int*)d_in[2];
    const int*   out_idx = (const int*)d_in[3];
    const int*   out_mask= (const int*)d_in[4];
    const float* W0      = (const float*)d_in[5];
    const float* b0      = (const float*)d_in[6];
    const float* W1      = (const float*)d_in[7];
    const float* b1      = (const float*)d_in[8];
    const float* Wout    = (const float*)d_in[9];
    const float* bout    = (const float*)d_in[10];
    float* out = (float*)d_out;

    cudaFuncSetAttribute(fused_kernel,
                         cudaFuncAttributeMaxDynamicSharedMemorySize,
                         SMEM_TOTAL);
    fused_kernel<<<GRID_CTAS, 128, SMEM_TOTAL>>>(
        edges, in_idx, in_mask, out_idx, out_mask,
        W0, b0, W1, b1, Wout, bout, out);
}

// round 17
// speedup vs baseline: 1.3437x; 1.3437x over previous
#include <cuda_runtime.h>
#include <cuda_bf16.h>
#include <cuda_fp16.h>
#include <math.h>
#include <stdint.h>

// Problem constants: N=200000, K_IN=8, K_OUT=4, E=800000, D=64, H=128, O=1
#define D_DIM 64
#define K_IN 8
#define K_OUT 4
#define H_DIM 128
#define TILE_M 64
#define N_TILES 12500       // 800000 rows / 64 rows per tile
#define GRID_CTAS 296       // 2 persistent CTAs per SM

// ---------------------------------------------------------------------------
// helpers
// ---------------------------------------------------------------------------
__device__ __forceinline__ uint32_t smem_u32(const void* p) {
    uint32_t a;
    asm("{ .reg .u64 t; cvta.to.shared.u64 t, %1; cvt.u32.u64 %0, t; }"
        : "=r"(a) : "l"(p));
    return a;
}

// pack two floats to f16x2: lo -> bits[15:0], hi -> bits[31:16]
__device__ __forceinline__ uint32_t f16x2_rn(float lo, float hi) {
    uint32_t r;
    asm("cvt.rn.f16x2.f32 %0, %1, %2;" : "=r"(r) : "f"(hi), "f"(lo));
    return r;
}

// convert 8 fp32 to single fp16 16B chunk
__device__ __forceinline__ uint4 cvt8h(const float* f) {
    uint4 v;
    v.x = f16x2_rn(f[0], f[1]); v.y = f16x2_rn(f[2], f[3]);
    v.z = f16x2_rn(f[4], f[5]); v.w = f16x2_rn(f[6], f[7]);
    return v;
}

#define LDMX4(r0, r1, r2, r3, addr) \
    asm volatile("ldmatrix.sync.aligned.m8n8.x4.shared.b16 {%0,%1,%2,%3}, [%4];" \
        : "=r"(r0), "=r"(r1), "=r"(r2), "=r"(r3) : "r"(addr))

#define MMAF16(c, a, b) \
    asm volatile("mma.sync.aligned.m16n8k16.row.col.f32.f16.f16.f32 " \
        "{%0,%1,%2,%3}, {%4,%5,%6,%7}, {%8,%9}, {%0,%1,%2,%3};" \
        : "+f"((c)[0]), "+f"((c)[1]), "+f"((c)[2]), "+f"((c)[3]) \
        : "r"((a)[0]), "r"((a)[1]), "r"((a)[2]), "r"((a)[3]), \
          "r"((b)[0]), "r"((b)[1]))

// ---------------------------------------------------------------------------
// SMEM layout (bytes), TWO CTAs per SM:
//   XB  @ 0      [64 m][128 k] fp16 X    (16 KB)  256B rows, XOR-16B swizzle
//   HB  @ 16384  [64 m][128 h] fp16 H    (16 KB)
//   W0  @ 32768  [128 h][128 k] fp16     (32 KB)
//   W1  @ 65536  (32 KB)
//   STG @ 98304  4 x 64 fp32 partials (1 KB)
// Total 99328 bytes per CTA -> 2 CTAs/SM.
// ---------------------------------------------------------------------------
#define XB_B    0u
#define HB_B    16384u
#define W0_B    32768u
#define W1_B    65536u
#define STG_B   98304u
#define SMEM_TOTAL 99328

__device__ __forceinline__ uint32_t swz(int row, int chunk) {
    return (uint32_t)row * 256u + (uint32_t)((chunk ^ (row & 7)) << 4);
}

// 1-pass GEMM over k=128 (A single fp16), warp tile 32m x 32n: acc += A * W
__device__ __forceinline__ void gemm_1pass(
    uint32_t AB, uint32_t WB,
    uint32_t aOff0, uint32_t aOff1, uint32_t aKey, uint32_t cbA,
    uint32_t bOff0, uint32_t bOff1, uint32_t bKey, uint32_t cbB,
    float acc[2][4][4])
{
#pragma unroll
    for (int kc = 0; kc < 8; ++kc) {
        uint32_t ca = (uint32_t)((((uint32_t)(2 * kc) + cbA) ^ aKey) << 4);
        uint32_t cb = (uint32_t)((((uint32_t)(2 * kc) + cbB) ^ bKey) << 4);
        uint32_t a0[4], a1[4], bq0[4], bq1[4];
        LDMX4(a0[0], a0[1], a0[2], a0[3], AB + aOff0 + ca);
        LDMX4(a1[0], a1[1], a1[2], a1[3], AB + aOff1 + ca);
        LDMX4(bq0[0], bq0[1], bq0[2], bq0[3], WB + bOff0 + cb);
        LDMX4(bq1[0], bq1[1], bq1[2], bq1[3], WB + bOff1 + cb);
        MMAF16(acc[0][0], a0, bq0 + 0);
        MMAF16(acc[0][1], a0, bq0 + 2);
        MMAF16(acc[0][2], a0, bq1 + 0);
        MMAF16(acc[0][3], a0, bq1 + 2);
        MMAF16(acc[1][0], a1, bq0 + 0);
        MMAF16(acc[1][1], a1, bq0 + 2);
        MMAF16(acc[1][2], a1, bq1 + 0);
        MMAF16(acc[1][3], a1, bq1 + 2);
    }
}

// ---------------------------------------------------------------------------
// Register-only attention for one node (see R12 notes). Pooled written
// directly into X pooled-half (single fp16) rows 4*nlocal..+3, cols 64..127.
// ---------------------------------------------------------------------------
__device__ __forceinline__ void attn_node(
    const float2* r, int m_l, int ln, char* smem, int nlocal)
{
    const unsigned FULL = 0xffffffffu;
    const int sel1 = (ln >> 4) & 1;
    const int sel2 = (ln >> 3) & 1;
    const int sel3 = (ln >> 2) & 1;
    const int sel4 = (ln >> 1) & 1;
    const int sel5 = ln & 1;

    float h1[32];
#pragma unroll
    for (int i = 0; i < 32; ++i) {
        const int qa = i >> 3, ka = i & 7;
        float da = r[qa].x * r[ka].x + r[qa].y * r[ka].y;
        float db = r[qa + 4].x * r[ka].x + r[qa + 4].y * r[ka].y;
        float mine  = sel1 ? db : da;
        float their = sel1 ? da : db;
        h1[i] = mine + __shfl_xor_sync(FULL, their, 16);
    }
    float h2[16];
#pragma unroll
    for (int i = 0; i < 16; ++i) {
        float mine  = sel2 ? h1[i + 16] : h1[i];
        float their = sel2 ? h1[i] : h1[i + 16];
        h2[i] = mine + __shfl_xor_sync(FULL, their, 8);
    }
    float h3[8];
#pragma unroll
    for (int i = 0; i < 8; ++i) {
        float mine  = sel3 ? h2[i + 8] : h2[i];
        float their = sel3 ? h2[i] : h2[i + 8];
        h3[i] = mine + __shfl_xor_sync(FULL, their, 4);
    }
    float h4[4];
#pragma unroll
    for (int i = 0; i < 4; ++i) {
        float mine  = sel4 ? h3[i + 4] : h3[i];
        float their = sel4 ? h3[i] : h3[i + 4];
        h4[i] = mine + __shfl_xor_sync(FULL, their, 2);
    }
    float s0, s1;
    {
        float mine0  = sel5 ? h4[2] : h4[0];
        float their0 = sel5 ? h4[0] : h4[2];
        float mine1  = sel5 ? h4[3] : h4[1];
        float their1 = sel5 ? h4[1] : h4[3];
        s0 = (mine0 + __shfl_xor_sync(FULL, their0, 1)) * 0.125f;
        s1 = (mine1 + __shfl_xor_sync(FULL, their1, 1)) * 0.125f;
    }

    const int k0 = 2 * (ln & 3);
    int mk0 = __shfl_sync(FULL, m_l, k0);
    int mk1 = __shfl_sync(FULL, m_l, k0 + 1);
    if (!mk0) s0 = -1e9f;
    if (!mk1) s1 = -1e9f;

    float mx = fmaxf(s0, s1);
    mx = fmaxf(mx, __shfl_xor_sync(FULL, mx, 1));
    mx = fmaxf(mx, __shfl_xor_sync(FULL, mx, 2));
    float e0 = __expf(s0 - mx), e1 = __expf(s1 - mx);
    float z = e0 + e1;
    z += __shfl_xor_sync(FULL, z, 1);
    z += __shfl_xor_sync(FULL, z, 2);
    float a0 = e0 / z, a1 = e1 / z;

    int mq = __shfl_sync(FULL, m_l, ln >> 2);
    float v0 = mq ? a0 : 0.f, v1 = mq ? a1 : 0.f;
#pragma unroll
    for (int o = 4; o < 32; o <<= 1) {
        v0 += __shfl_xor_sync(FULL, v0, o);
        v1 += __shfl_xor_sync(FULL, v1, o);
    }
    int cnt = __popc(__ballot_sync(FULL, m_l != 0));
    float inv_denom = 1.f / fmaxf((float)cnt, 1.f);

    float px = 0.f, py = 0.f;
#pragma unroll
    for (int k = 0; k < 8; ++k) {
        float wk = (k & 1) ? __shfl_sync(FULL, v1, k >> 1)
                           : __shfl_sync(FULL, v0, k >> 1);
        px += wk * r[k].x;
        py += wk * r[k].y;
    }
    px *= inv_denom;
    py *= inv_denom;

    uint32_t hw = f16x2_rn(px, py);
    const int chunk = 8 + (ln >> 2);
    const uint32_t cof = (uint32_t)((ln & 3) * 4);
#pragma unroll
    for (int rr = 0; rr < 4; ++rr) {
        int row = nlocal * 4 + rr;
        uint32_t off = (uint32_t)row * 256u
                     + (uint32_t)((chunk ^ (row & 7)) << 4) + cof;
        *(uint32_t*)(smem + XB_B + off) = hw;
    }
}

// ---------------------------------------------------------------------------
// attention (2 nodes/warp) + edge-half X fill, with prefetched indices.
// ---------------------------------------------------------------------------
__device__ __forceinline__ void attn_and_fill(
    const float* __restrict__ edges, char* smem,
    int idxA, int mA, int idxB, int mB, int eidx,
    int lane, int w, int xrow, int xq)
{
    const unsigned FULL = 0xffffffffu;
    float2 rA[K_IN], rB[K_IN];
#pragma unroll
    for (int k = 0; k < K_IN; ++k) {
        int ek = __shfl_sync(FULL, idxA, k);
        rA[k] = *(const float2*)(edges + (size_t)ek * D_DIM + lane * 2);
    }
#pragma unroll
    for (int k = 0; k < K_IN; ++k) {
        int ek = __shfl_sync(FULL, idxB, k);
        rB[k] = *(const float2*)(edges + (size_t)ek * D_DIM + lane * 2);
    }
    // edge-half X fill (independent of attention math; loads issued here too)
    {
        const float4* s4 = (const float4*)(edges + (size_t)eidx * D_DIM
                                           + xq * 16);
        float4 f0a = s4[0], f1a = s4[1], f0b = s4[2], f1b = s4[3];
        float fa[8] = {f0a.x, f0a.y, f0a.z, f0a.w, f1a.x, f1a.y, f1a.z, f1a.w};
        float fb[8] = {f0b.x, f0b.y, f0b.z, f0b.w, f1b.x, f1b.y, f1b.z, f1b.w};
        *(uint4*)(smem + XB_B + swz(xrow, 2 * xq))     = cvt8h(fa);
        *(uint4*)(smem + XB_B + swz(xrow, 2 * xq + 1)) = cvt8h(fb);
    }
    attn_node(rA, mA, lane, smem, w * 2);
    attn_node(rB, mB, lane, smem, w * 2 + 1);
}

// ---------------------------------------------------------------------------
// Persistent fused kernel, software-pipelined:
//   prologue: attn+fill(tile0); barrier
//   loop: prefetch idx(next); GEMM1; epi1; B; attn+fill(next); GEMM2; epi2;
//         stage; C; out
// 2 barriers per tile.
// ---------------------------------------------------------------------------
__global__ void __launch_bounds__(256, 2) fused_kernel(
    const float* __restrict__ edges,
    const int* __restrict__ in_idx,
    const int* __restrict__ in_mask,
    const int* __restrict__ out_idx,
    const int* __restrict__ out_mask,
    const float* __restrict__ W0,
    const float* __restrict__ b0,
    const float* __restrict__ W1,
    const float* __restrict__ b1,
    const float* __restrict__ Wout,
    const float* __restrict__ bout,
    float* __restrict__ out)
{
    extern __shared__ char smem[];
    const uint32_t sb = smem_u32(smem);
    const unsigned FULL = 0xffffffffu;

    const int t    = threadIdx.x;
    const int lane = t & 31;
    const int w    = t >> 5;        // 0..7

    // ---- load W0/W1 -> single fp16 smem, ONCE ----
    {
        const int h = t & 127;
        const int q = t >> 7;       // 0..1
        const int key = h & 7;
        const float4* s0 = (const float4*)(W0 + (size_t)h * H_DIM + q * 64);
        const float4* s1 = (const float4*)(W1 + (size_t)h * H_DIM + q * 64);
#pragma unroll
        for (int c = 0; c < 8; ++c) {
            int chunk = q * 8 + c;
            uint32_t off = (uint32_t)h * 256u + (uint32_t)((chunk ^ key) << 4);
            {
                float4 f0 = s0[2 * c], f1 = s0[2 * c + 1];
                float f[8] = {f0.x, f0.y, f0.z, f0.w, f1.x, f1.y, f1.z, f1.w};
                *(uint4*)(smem + W0_B + off) = cvt8h(f);
            }
            {
                float4 f0 = s1[2 * c], f1 = s1[2 * c + 1];
                float f[8] = {f0.x, f0.y, f0.z, f0.w, f1.x, f1.y, f1.z, f1.w};
                *(uint4*)(smem + W1_B + off) = cvt8h(f);
            }
        }
    }

    // ---- per-lane GEMM geometry (warp grid 2m x 4n, warp tile 32m x 32n) ----
    const int m0  = (w & 1) * 32;
    const int n0  = (w >> 1) * 32;
    const int gid = lane >> 2;      // 0..7
    const int tig = lane & 3;       // 0..3
    const int sub = lane >> 3;      // 0..3
    const int r8  = lane & 7;
    const int aRow = m0 + (sub & 1) * 8 + r8;
    const uint32_t aOff0 = (uint32_t)aRow * 256u;
    const uint32_t aOff1 = (uint32_t)(aRow + 16) * 256u;
    const uint32_t aKey  = (uint32_t)r8;
    const uint32_t cbA   = (uint32_t)(sub >> 1);
    const int bRow = n0 + (sub >> 1) * 8 + r8;
    const uint32_t bOff0 = (uint32_t)bRow * 256u;
    const uint32_t bOff1 = (uint32_t)(bRow + 16) * 256u;
    const uint32_t bKey  = (uint32_t)r8;
    const uint32_t cbB   = (uint32_t)(sub & 1);

    float* stage = (float*)(smem + STG_B);

    // X-fill roles: 4 threads per row, 16 k each
    const int xrow = t & 63;
    const int xq   = t >> 6;        // 0..3

    // ---- prologue: first tile's attention + X fill ----
    int tile = blockIdx.x;
    {
        const int nodeA = tile * 16 + w * 2;
        int idxA = 0, mA = 0, idxB = 0, mB = 0;
        if (lane < K_IN) {
            idxA = in_idx[(size_t)nodeA * K_IN + lane];
            mA   = in_mask[(size_t)nodeA * K_IN + lane];
            idxB = in_idx[(size_t)(nodeA + 1) * K_IN + lane];
            mB   = in_mask[(size_t)(nodeA + 1) * K_IN + lane];
        }
        int eidx = out_idx[(size_t)tile * TILE_M + xrow];
        attn_and_fill(edges, smem, idxA, mA, idxB, mB, eidx,
                      lane, w, xrow, xq);
    }
    __syncthreads();   // X + W ready

    for (; tile < N_TILES; tile += gridDim.x) {
        const long base = (long)tile * TILE_M;
        const int next = tile + (int)gridDim.x;
        const bool hasNext = (next < N_TILES);

        // ---- prefetch next-tile indices (latency hides under GEMM1) ----
        int nIdxA = 0, nMA = 0, nIdxB = 0, nMB = 0, nEidx = 0;
        if (hasNext) {
            const int nodeA = next * 16 + w * 2;
            if (lane < K_IN) {
                nIdxA = in_idx[(size_t)nodeA * K_IN + lane];
                nMA   = in_mask[(size_t)nodeA * K_IN + lane];
                nIdxB = in_idx[(size_t)(nodeA + 1) * K_IN + lane];
                nMB   = in_mask[(size_t)(nodeA + 1) * K_IN + lane];
            }
            nEidx = out_idx[(size_t)next * TILE_M + xrow];
        }

        // ============ GEMM layer 1 (A = XB) ============
        float acc[2][4][4];
#pragma unroll
        for (int i = 0; i < 2; ++i)
#pragma unroll
            for (int j = 0; j < 4; ++j)
#pragma unroll
                for (int p = 0; p < 4; ++p) acc[i][j][p] = 0.f;

        gemm_1pass(sb + XB_B, sb + W0_B,
                   aOff0, aOff1, aKey, cbA, bOff0, bOff1, bKey, cbB, acc);

        // ---- epilogue 1: H = relu(acc + b0) -> HB ----
#pragma unroll
        for (int j = 0; j < 4; ++j) {
            int h0 = n0 + 8 * j + 2 * tig;
            float2 bb = *(const float2*)(b0 + h0);
            int chunk = (n0 + 8 * j) >> 3;
            uint32_t cof = (uint32_t)(tig * 4);
#pragma unroll
            for (int i = 0; i < 2; ++i) {
#pragma unroll
                for (int rs = 0; rs < 2; ++rs) {
                    int row = m0 + 16 * i + 8 * rs + gid;
                    float v0 = fmaxf(acc[i][j][2 * rs]     + bb.x, 0.f);
                    float v1 = fmaxf(acc[i][j][2 * rs + 1] + bb.y, 0.f);
                    uint32_t hw = f16x2_rn(v0, v1);
                    uint32_t off = (uint32_t)row * 256u
                                 + (uint32_t)((chunk ^ (row & 7)) << 4) + cof;
                    *(uint32_t*)(smem + HB_B + off) = hw;
                }
            }
        }
        __syncthreads();   // barrier B: HB ready; XB reads complete (XB dead)

        // ---- next tile's attention + X fill into (dead) XB ----
        if (hasNext) {
            attn_and_fill(edges, smem, nIdxA, nMA, nIdxB, nMB, nEidx,
                          lane, w, xrow, xq);
        }

        // ============ GEMM layer 2 (A = HB) ============
#pragma unroll
        for (int i = 0; i < 2; ++i)
#pragma unroll
            for (int j = 0; j < 4; ++j)
#pragma unroll
                for (int p = 0; p < 4; ++p) acc[i][j][p] = 0.f;

        gemm_1pass(sb + HB_B, sb + W1_B,
                   aOff0, aOff1, aKey, cbA, bOff0, bOff1, bKey, cbB, acc);

        // ---- final epilogue: relu(+b1), dot Wout, reduce ----
        float y[2][2] = {{0.f, 0.f}, {0.f, 0.f}};
#pragma unroll
        for (int j = 0; j < 4; ++j) {
            int h0 = n0 + 8 * j + 2 * tig;
            float2 bb = *(const float2*)(b1 + h0);
            float2 ww = *(const float2*)(Wout + h0);
#pragma unroll
            for (int i = 0; i < 2; ++i) {
#pragma unroll
                for (int rs = 0; rs < 2; ++rs) {
                    float v0 = fmaxf(acc[i][j][2 * rs]     + bb.x, 0.f);
                    float v1 = fmaxf(acc[i][j][2 * rs + 1] + bb.y, 0.f);
                    y[i][rs] += ww.x * v0 + ww.y * v1;
                }
            }
        }
#pragma unroll
        for (int i = 0; i < 2; ++i)
#pragma unroll
            for (int rs = 0; rs < 2; ++rs) {
                y[i][rs] += __shfl_xor_sync(FULL, y[i][rs], 1);
                y[i][rs] += __shfl_xor_sync(FULL, y[i][rs], 2);
            }

        if (tig == 0) {
            int col = w >> 1;
#pragma unroll
            for (int i = 0; i < 2; ++i)
#pragma unroll
                for (int rs = 0; rs < 2; ++rs) {
                    int row = m0 + 16 * i + 8 * rs + gid;
                    stage[col * TILE_M + row] = y[i][rs];
                }
        }
        __syncthreads();   // barrier C: stage ready; XB writes complete

        if (t < TILE_M) {
            long row = base + t;
            float s = stage[t] + stage[64 + t] + stage[128 + t]
                    + stage[192 + t] + bout[0];
            out[row] = s * (float)out_mask[row];
        }
        // no barrier D: next-iter stage writes are ordered after barrier B'
        // (every thread's out-read precedes its B' arrival), and next-iter
        // GEMM1's XB reads are ordered after barrier C above.
    }
}

// ---------------------------------------------------------------------------
extern "C" void kernel_launch(void* const* d_in, const int* in_sizes, int n_in,
                              void* d_out, int out_size) {
    const float* edges   = (const float*)d_in[0];
    const int*   in_idx  = (const int*)d_in[1];
    const int*   in_mask = (const int*)d_in[2];
    const int*   out_idx = (const int*)d_in[3];
    const int*   out_mask= (const int*)d_in[4];
    const float* W0      = (const float*)d_in[5];
    const float* b0      = (const float*)d_in[6];
    const float* W1      = (const float*)d_in[7];
    const float* b1      = (const float*)d_in[8];
    const float* Wout    = (const float*)d_in[9];
    const float* bout    = (const float*)d_in[10];
    float* out = (float*)d_out;

    cudaFuncSetAttribute(fused_kernel,
                         cudaFuncAttributeMaxDynamicSharedMemorySize,
                         SMEM_TOTAL);
    fused_kernel<<<GRID_CTAS, 256, SMEM_TOTAL>>>(
        edges, in_idx, in_mask, out_idx, out_mask,
        W0, b0, W1, b1, Wout, bout, out);
}